// round 3
// baseline (speedup 1.0000x reference)
#include <cuda_runtime.h>
#include <cstdint>
#include <cstddef>

#define NBATCH 256
#define NT     2048
#define NFIN   32
#define NHID   64
#define NGATE  256
#define NPOS   (NBATCH * NT)   // 524288

// ---------------- scratch (static device globals: allocation-free) ----------
__device__ float g_env0[(size_t)NBATCH * NT * NHID];   // layer-0 LSTM output
__device__ float g_env1[(size_t)NBATCH * NT * NHID];   // layer-1 LSTM output
__device__ float g_traj[366 * 8];                      // ODE trajectory

// ---------------- fast activations (fp32, ~1e-6 rel err) -------------------
__device__ __forceinline__ float fsig(float x) {
    return __fdividef(1.0f, 1.0f + __expf(-x));
}
__device__ __forceinline__ float ftanh(float x) {
    float ax = fabsf(x);
    float e  = __expf(-2.0f * ax);
    float r  = __fdividef(1.0f - e, 1.0f + e);
    return copysignf(r, x);
}

// ---------------- ODE body (runs as blockIdx == NBATCH of kernel L0) -------
__device__ void ode_body(int tid,
                         const float* __restrict__ h0,
                         const float* __restrict__ W1, const float* __restrict__ b1,
                         const float* __restrict__ W2, const float* __restrict__ b2,
                         const float* __restrict__ W3, const float* __restrict__ b3)
{
    __shared__ float sInp[12];
    __shared__ float sz1[64];
    __shared__ float sz2[64];
    __shared__ float sk[6][8];
    __shared__ float shh[8];
    __shared__ __align__(16) float sW3[8 * 64];
    __shared__ float sb3[8];

    float w1r[9];
    float w2r[64];
    float b1j = 0.f, b2j = 0.f;
    if (tid < 64) {
#pragma unroll
        for (int k = 0; k < 9; ++k) w1r[k] = W1[tid * 9 + k];
#pragma unroll
        for (int k = 0; k < 64; ++k) w2r[k] = W2[tid * 64 + k];
        b1j = b1[tid];
        b2j = b2[tid];
    }
    for (int i = tid; i < 8 * 64; i += 256) sW3[i] = W3[i];
    if (tid < 8) {
        sb3[tid] = b3[tid];
        shh[tid] = h0[tid];
        g_traj[tid] = h0[tid];
    }
    __syncthreads();

    const float dt = 1.0f / 365.0f;

    for (int d = 0; d < 365; ++d) {
        float t0 = (float)d * dt;
#pragma unroll 1
        for (int s = 0; s < 6; ++s) {
            if (tid < 8) {
                float v = shh[tid];
                if (s == 1) v += dt * (0.2f * sk[0][tid]);
                else if (s == 2) v += dt * ((3.f/40.f)*sk[0][tid] + (9.f/40.f)*sk[1][tid]);
                else if (s == 3) v += dt * ((44.f/45.f)*sk[0][tid] - (56.f/15.f)*sk[1][tid] + (32.f/9.f)*sk[2][tid]);
                else if (s == 4) v += dt * ((19372.f/6561.f)*sk[0][tid] - (25360.f/2187.f)*sk[1][tid]
                                          + (64448.f/6561.f)*sk[2][tid] - (212.f/729.f)*sk[3][tid]);
                else if (s == 5) v += dt * ((9017.f/3168.f)*sk[0][tid] - (355.f/33.f)*sk[1][tid]
                                          + (46732.f/5247.f)*sk[2][tid] + (49.f/176.f)*sk[3][tid]
                                          - (5103.f/18656.f)*sk[4][tid]);
                sInp[tid] = v;
            }
            if (tid == 8) {
                float cn;
                if (s == 0) cn = 0.0f;
                else if (s == 1) cn = 0.2f;
                else if (s == 2) cn = 0.3f;
                else if (s == 3) cn = 0.8f;
                else if (s == 4) cn = 8.f/9.f;
                else cn = 1.0f;
                sInp[8] = t0 + cn * dt;
            }
            __syncthreads();
            if (tid < 64) {
                float a = b1j;
#pragma unroll
                for (int k = 0; k < 9; ++k) a = fmaf(w1r[k], sInp[k], a);
                sz1[tid] = ftanh(a);
            }
            __syncthreads();
            if (tid < 64) {
                float a0 = b2j, a1 = 0.f, a2 = 0.f, a3 = 0.f;
#pragma unroll
                for (int k = 0; k < 64; k += 4) {
                    a0 = fmaf(w2r[k+0], sz1[k+0], a0);
                    a1 = fmaf(w2r[k+1], sz1[k+1], a1);
                    a2 = fmaf(w2r[k+2], sz1[k+2], a2);
                    a3 = fmaf(w2r[k+3], sz1[k+3], a3);
                }
                sz2[tid] = ftanh((a0 + a1) + (a2 + a3));
            }
            __syncthreads();
            if (tid < 8) {
                float a0 = sb3[tid], a1 = 0.f, a2 = 0.f, a3 = 0.f;
#pragma unroll
                for (int k = 0; k < 64; k += 4) {
                    a0 = fmaf(sW3[tid*64 + k+0], sz2[k+0], a0);
                    a1 = fmaf(sW3[tid*64 + k+1], sz2[k+1], a1);
                    a2 = fmaf(sW3[tid*64 + k+2], sz2[k+2], a2);
                    a3 = fmaf(sW3[tid*64 + k+3], sz2[k+3], a3);
                }
                sk[s][tid] = (a0 + a1) + (a2 + a3);
            }
            __syncthreads();
        }
        if (tid < 8) {
            float hn = shh[tid] + dt * ((35.f/384.f)   * sk[0][tid]
                                      + (500.f/1113.f) * sk[2][tid]
                                      + (125.f/192.f)  * sk[3][tid]
                                      - (2187.f/6784.f)* sk[4][tid]
                                      + (11.f/84.f)    * sk[5][tid]);
            shh[tid] = hn;
            g_traj[(d + 1) * 8 + tid] = hn;
        }
        __syncthreads();
    }
}

// ---------------- Kernel A: LSTM layer 0 (+ hidden ODE CTA) ----------------
// grid = 257 CTAs x 256 threads. blockIdx < 256: one batch row each.
// Thread t owns gate t: Wih row (32 regs) + Whh row (64 regs) in registers.
__global__ __launch_bounds__(256, 2) void k_lstm0_ode(
    const float* __restrict__ X,
    const float* __restrict__ Wih, const float* __restrict__ Whh,
    const float* __restrict__ bih, const float* __restrict__ bhh,
    const float* __restrict__ h0,
    const float* __restrict__ oW1, const float* __restrict__ ob1,
    const float* __restrict__ oW2, const float* __restrict__ ob2,
    const float* __restrict__ oW3, const float* __restrict__ ob3)
{
    const int t = threadIdx.x;
    if (blockIdx.x >= NBATCH) {
        ode_body(t, h0, oW1, ob1, oW2, ob2, oW3, ob3);
        return;
    }
    const int b = blockIdx.x;

    float wih[NFIN];
#pragma unroll
    for (int k = 0; k < NFIN; ++k) wih[k] = Wih[t * NFIN + k];
    float whh[NHID];
#pragma unroll
    for (int k = 0; k < NHID; ++k) whh[k] = Whh[t * NHID + k];
    const float bias = bih[t] + bhh[t];

    __shared__ __align__(16) float xs[2][NFIN];
    __shared__ float act[NGATE];
    __shared__ __align__(16) float hs[NHID];
    if (t < NHID) hs[t] = 0.0f;

    const float* xrow = X + (size_t)b * NT * NFIN;
    if (t < 8) ((float4*)xs[0])[t] = ((const float4*)xrow)[t];
    __syncthreads();

    float c = 0.0f;
    float* eout = g_env0 + (size_t)b * NT * NHID;
    int cur = 0;

    for (int step = 0; step < NT; ++step) {
        // prefetch next x into the other buffer
        if (t < 8) {
            int nxt = (step + 1 < NT) ? (step + 1) : step;
            ((float4*)xs[cur ^ 1])[t] = ((const float4*)(xrow + (size_t)nxt * NFIN))[t];
        }
        float a0 = bias, a1 = 0.f, a2 = 0.f, a3 = 0.f;
#pragma unroll
        for (int k = 0; k < NFIN; k += 4) {
            float4 v = *(const float4*)(xs[cur] + k);
            a0 = fmaf(wih[k+0], v.x, a0);
            a1 = fmaf(wih[k+1], v.y, a1);
            a2 = fmaf(wih[k+2], v.z, a2);
            a3 = fmaf(wih[k+3], v.w, a3);
        }
#pragma unroll
        for (int k = 0; k < NHID; k += 4) {
            float4 v = *(const float4*)(hs + k);
            a0 = fmaf(whh[k+0], v.x, a0);
            a1 = fmaf(whh[k+1], v.y, a1);
            a2 = fmaf(whh[k+2], v.z, a2);
            a3 = fmaf(whh[k+3], v.w, a3);
        }
        float g = (a0 + a1) + (a2 + a3);
        float a = (t >= 128 && t < 192) ? ftanh(g) : fsig(g);
        act[t] = a;
        __syncthreads();
        if (t < NHID) {
            c = act[64 + t] * c + act[t] * act[128 + t];
            float h = act[192 + t] * ftanh(c);
            hs[t] = h;
            eout[(size_t)step * NHID + t] = h;
        }
        cur ^= 1;
        __syncthreads();
    }
}

// ---------------- Kernel B: LSTM layer 1 ------------------------------------
__global__ __launch_bounds__(256) void k_lstm1(
    const float* __restrict__ Wih, const float* __restrict__ Whh,
    const float* __restrict__ bih, const float* __restrict__ bhh)
{
    const int t = threadIdx.x;
    const int b = blockIdx.x;

    float wih[NHID];
#pragma unroll
    for (int k = 0; k < NHID; ++k) wih[k] = Wih[t * NHID + k];
    float whh[NHID];
#pragma unroll
    for (int k = 0; k < NHID; ++k) whh[k] = Whh[t * NHID + k];
    const float bias = bih[t] + bhh[t];

    __shared__ __align__(16) float es[2][NHID];
    __shared__ float act[NGATE];
    __shared__ __align__(16) float hs[NHID];
    if (t < NHID) hs[t] = 0.0f;

    const float* erow = g_env0 + (size_t)b * NT * NHID;
    if (t < 16) ((float4*)es[0])[t] = ((const float4*)erow)[t];
    __syncthreads();

    float c = 0.0f;
    float* eout = g_env1 + (size_t)b * NT * NHID;
    int cur = 0;

    for (int step = 0; step < NT; ++step) {
        if (t < 16) {
            int nxt = (step + 1 < NT) ? (step + 1) : step;
            ((float4*)es[cur ^ 1])[t] = ((const float4*)(erow + (size_t)nxt * NHID))[t];
        }
        float a0 = bias, a1 = 0.f, a2 = 0.f, a3 = 0.f;
#pragma unroll
        for (int k = 0; k < NHID; k += 4) {
            float4 v = *(const float4*)(es[cur] + k);
            a0 = fmaf(wih[k+0], v.x, a0);
            a1 = fmaf(wih[k+1], v.y, a1);
            a2 = fmaf(wih[k+2], v.z, a2);
            a3 = fmaf(wih[k+3], v.w, a3);
        }
#pragma unroll
        for (int k = 0; k < NHID; k += 4) {
            float4 v = *(const float4*)(hs + k);
            a0 = fmaf(whh[k+0], v.x, a0);
            a1 = fmaf(whh[k+1], v.y, a1);
            a2 = fmaf(whh[k+2], v.z, a2);
            a3 = fmaf(whh[k+3], v.w, a3);
        }
        float g = (a0 + a1) + (a2 + a3);
        float a = (t >= 128 && t < 192) ? ftanh(g) : fsig(g);
        act[t] = a;
        __syncthreads();
        if (t < NHID) {
            c = act[64 + t] * c + act[t] * act[128 + t];
            float h = act[192 + t] * ftanh(c);
            hs[t] = h;
            eout[(size_t)step * NHID + t] = h;
        }
        cur ^= 1;
        __syncthreads();
    }
}

// ---------------- Kernel C: physics + fusion MLP + outputs ------------------
// thread-per-position; weights broadcast from SMEM (float4 => 1 LDS / 4 FMA).
__global__ __launch_bounds__(256) void k_fusion(
    const int*   __restrict__ day_ids,
    const float* __restrict__ raw,
    const float* __restrict__ hdw, const float* __restrict__ hdb,
    const float* __restrict__ fW1, const float* __restrict__ fb1,
    const float* __restrict__ fW2, const float* __restrict__ fb2,
    const float* __restrict__ rW1, const float* __restrict__ rb1,
    const float* __restrict__ rW2, const float* __restrict__ rb2,
    float* __restrict__ out)
{
    const int tid = threadIdx.x;

    __shared__ __align__(16) float sW1[64 * 76];   // fus_W1 padded 73 -> 76
    __shared__ __align__(16) float sW2[64 * 64];
    __shared__ __align__(16) float sR1[32 * 64];
    __shared__ float sR2[32];
    __shared__ float sb1[64], sb2[64], srb1[32];
    __shared__ float shdw[8];
    __shared__ float sscal[2];

    for (int i = tid; i < 64 * 76; i += 256) {
        int j = i / 76, k = i - j * 76;
        sW1[i] = (k < 73) ? fW1[j * 73 + k] : 0.0f;
    }
    for (int i = tid; i < 64 * 64; i += 256) sW2[i] = fW2[i];
    for (int i = tid; i < 32 * 64; i += 256) sR1[i] = rW1[i];
    if (tid < 64) { sb1[tid] = fb1[tid]; sb2[tid] = fb2[tid]; }
    if (tid < 32) { sR2[tid] = rW2[tid]; srb1[tid] = rb1[tid]; }
    if (tid < 8)  shdw[tid] = hdw[tid];
    if (tid == 0) { sscal[0] = hdb[0]; sscal[1] = rb2[0]; }
    __syncthreads();

    const int idx = blockIdx.x * 256 + tid;       // grid = 2048 -> idx < NPOS
    const int b = idx >> 11;

    float z[76];
    const float4* ep = (const float4*)(g_env1 + (size_t)idx * NHID);
#pragma unroll
    for (int i = 0; i < 16; ++i) {
        float4 v = ep[i];
        z[4*i+0] = v.x; z[4*i+1] = v.y; z[4*i+2] = v.z; z[4*i+3] = v.w;
    }
    const int day = day_ids[b];
    float health[8];
#pragma unroll
    for (int i = 0; i < 8; ++i) { health[i] = g_traj[day * 8 + i]; z[64 + i] = health[i]; }

    float4 rv = ((const float4*)raw)[idx];
    float iphys = rv.x * 9.0f * (1.0f + 0.0005f * (rv.y - 0.5f));
    z[72] = iphys; z[73] = 0.f; z[74] = 0.f; z[75] = 0.f;

    float rawD = sscal[0];
#pragma unroll
    for (int i = 0; i < 8; ++i) rawD = fmaf(health[i], shdw[i], rawD);
    float D = fsig(rawD);

    // feat1 = relu(fus_W1 @ z + fb1)
    float f1[64];
#pragma unroll
    for (int j = 0; j < 64; j += 4) {
        float a0 = sb1[j], a1 = sb1[j+1], a2 = sb1[j+2], a3 = sb1[j+3];
#pragma unroll
        for (int k = 0; k < 76; k += 4) {
            float4 w0 = *(const float4*)(sW1 + (j+0) * 76 + k);
            float4 w1 = *(const float4*)(sW1 + (j+1) * 76 + k);
            float4 w2 = *(const float4*)(sW1 + (j+2) * 76 + k);
            float4 w3 = *(const float4*)(sW1 + (j+3) * 76 + k);
            a0 = fmaf(z[k], w0.x, a0); a0 = fmaf(z[k+1], w0.y, a0); a0 = fmaf(z[k+2], w0.z, a0); a0 = fmaf(z[k+3], w0.w, a0);
            a1 = fmaf(z[k], w1.x, a1); a1 = fmaf(z[k+1], w1.y, a1); a1 = fmaf(z[k+2], w1.z, a1); a1 = fmaf(z[k+3], w1.w, a1);
            a2 = fmaf(z[k], w2.x, a2); a2 = fmaf(z[k+1], w2.y, a2); a2 = fmaf(z[k+2], w2.z, a2); a2 = fmaf(z[k+3], w2.w, a2);
            a3 = fmaf(z[k], w3.x, a3); a3 = fmaf(z[k+1], w3.y, a3); a3 = fmaf(z[k+2], w3.z, a3); a3 = fmaf(z[k+3], w3.w, a3);
        }
        f1[j+0] = fmaxf(a0, 0.f); f1[j+1] = fmaxf(a1, 0.f);
        f1[j+2] = fmaxf(a2, 0.f); f1[j+3] = fmaxf(a3, 0.f);
    }

    // feat2 = relu(fus_W2 @ feat1 + fb2)
    float f2[64];
#pragma unroll
    for (int j = 0; j < 64; j += 4) {
        float a0 = sb2[j], a1 = sb2[j+1], a2 = sb2[j+2], a3 = sb2[j+3];
#pragma unroll
        for (int k = 0; k < 64; k += 4) {
            float4 w0 = *(const float4*)(sW2 + (j+0) * 64 + k);
            float4 w1 = *(const float4*)(sW2 + (j+1) * 64 + k);
            float4 w2 = *(const float4*)(sW2 + (j+2) * 64 + k);
            float4 w3 = *(const float4*)(sW2 + (j+3) * 64 + k);
            a0 = fmaf(f1[k], w0.x, a0); a0 = fmaf(f1[k+1], w0.y, a0); a0 = fmaf(f1[k+2], w0.z, a0); a0 = fmaf(f1[k+3], w0.w, a0);
            a1 = fmaf(f1[k], w1.x, a1); a1 = fmaf(f1[k+1], w1.y, a1); a1 = fmaf(f1[k+2], w1.z, a1); a1 = fmaf(f1[k+3], w1.w, a1);
            a2 = fmaf(f1[k], w2.x, a2); a2 = fmaf(f1[k+1], w2.y, a2); a2 = fmaf(f1[k+2], w2.z, a2); a2 = fmaf(f1[k+3], w2.w, a2);
            a3 = fmaf(f1[k], w3.x, a3); a3 = fmaf(f1[k+1], w3.y, a3); a3 = fmaf(f1[k+2], w3.z, a3); a3 = fmaf(f1[k+3], w3.w, a3);
        }
        f2[j+0] = fmaxf(a0, 0.f); f2[j+1] = fmaxf(a1, 0.f);
        f2[j+2] = fmaxf(a2, 0.f); f2[j+3] = fmaxf(a3, 0.f);
    }

    // r1 = relu(res_W1 @ feat2 + rb1)
    float r1[32];
#pragma unroll
    for (int j = 0; j < 32; j += 4) {
        float a0 = srb1[j], a1 = srb1[j+1], a2 = srb1[j+2], a3 = srb1[j+3];
#pragma unroll
        for (int k = 0; k < 64; k += 4) {
            float4 w0 = *(const float4*)(sR1 + (j+0) * 64 + k);
            float4 w1 = *(const float4*)(sR1 + (j+1) * 64 + k);
            float4 w2 = *(const float4*)(sR1 + (j+2) * 64 + k);
            float4 w3 = *(const float4*)(sR1 + (j+3) * 64 + k);
            a0 = fmaf(f2[k], w0.x, a0); a0 = fmaf(f2[k+1], w0.y, a0); a0 = fmaf(f2[k+2], w0.z, a0); a0 = fmaf(f2[k+3], w0.w, a0);
            a1 = fmaf(f2[k], w1.x, a1); a1 = fmaf(f2[k+1], w1.y, a1); a1 = fmaf(f2[k+2], w1.z, a1); a1 = fmaf(f2[k+3], w1.w, a1);
            a2 = fmaf(f2[k], w2.x, a2); a2 = fmaf(f2[k+1], w2.y, a2); a2 = fmaf(f2[k+2], w2.z, a2); a2 = fmaf(f2[k+3], w2.w, a2);
            a3 = fmaf(f2[k], w3.x, a3); a3 = fmaf(f2[k+1], w3.y, a3); a3 = fmaf(f2[k+2], w3.z, a3); a3 = fmaf(f2[k+3], w3.w, a3);
        }
        r1[j+0] = fmaxf(a0, 0.f); r1[j+1] = fmaxf(a1, 0.f);
        r1[j+2] = fmaxf(a2, 0.f); r1[j+3] = fmaxf(a3, 0.f);
    }

    // r = res_W2 @ r1 + rb2
    float a0 = sscal[1], a1 = 0.f, a2 = 0.f, a3 = 0.f;
#pragma unroll
    for (int k = 0; k < 32; k += 4) {
        a0 = fmaf(r1[k+0], sR2[k+0], a0);
        a1 = fmaf(r1[k+1], sR2[k+1], a1);
        a2 = fmaf(r1[k+2], sR2[k+2], a2);
        a3 = fmaf(r1[k+3], sR2[k+3], a3);
    }
    float r = (a0 + a1) + (a2 + a3);

    float ibase = D * iphys;
    out[(size_t)0 * NPOS + idx] = ibase + r;   // I_pred
    out[(size_t)1 * NPOS + idx] = iphys;       // I_phys
    out[(size_t)2 * NPOS + idx] = ibase;       // I_base
    out[(size_t)3 * NPOS + idx] = D;           // D
    out[(size_t)4 * NPOS + idx] = r;           // r
    float* ho = out + (size_t)5 * NPOS + (size_t)idx * 8;
#pragma unroll
    for (int i = 0; i < 8; ++i) ho[i] = health[i];  // health_seq
}

// ---------------- launch ----------------------------------------------------
extern "C" void kernel_launch(void* const* d_in, const int* in_sizes, int n_in,
                              void* d_out, int out_size)
{
    const float* X        = (const float*)d_in[0];
    const int*   day_ids  = (const int*)  d_in[1];
    const float* raw      = (const float*)d_in[2];
    const float* ih0      = (const float*)d_in[3];
    const float* oW1      = (const float*)d_in[4];
    const float* ob1      = (const float*)d_in[5];
    const float* oW2      = (const float*)d_in[6];
    const float* ob2      = (const float*)d_in[7];
    const float* oW3      = (const float*)d_in[8];
    const float* ob3      = (const float*)d_in[9];
    const float* Wih0     = (const float*)d_in[10];
    const float* Whh0     = (const float*)d_in[11];
    const float* bih0     = (const float*)d_in[12];
    const float* bhh0     = (const float*)d_in[13];
    const float* Wih1     = (const float*)d_in[14];
    const float* Whh1     = (const float*)d_in[15];
    const float* bih1     = (const float*)d_in[16];
    const float* bhh1     = (const float*)d_in[17];
    const float* hdw      = (const float*)d_in[18];
    const float* hdb      = (const float*)d_in[19];
    const float* fW1      = (const float*)d_in[20];
    const float* fb1      = (const float*)d_in[21];
    const float* fW2      = (const float*)d_in[22];
    const float* fb2      = (const float*)d_in[23];
    const float* rW1      = (const float*)d_in[24];
    const float* rb1      = (const float*)d_in[25];
    const float* rW2      = (const float*)d_in[26];
    const float* rb2      = (const float*)d_in[27];

    // Layer-0 LSTM over all 256 rows + ODE trajectory (extra CTA), concurrent.
    k_lstm0_ode<<<NBATCH + 1, 256>>>(X, Wih0, Whh0, bih0, bhh0,
                                     ih0, oW1, ob1, oW2, ob2, oW3, ob3);
    // Layer-1 LSTM.
    k_lstm1<<<NBATCH, 256>>>(Wih1, Whh1, bih1, bhh1);
    // Physics + fusion MLP + all outputs.
    k_fusion<<<NPOS / 256, 256>>>(day_ids, raw, hdw, hdb,
                                  fW1, fb1, fW2, fb2,
                                  rW1, rb1, rW2, rb2,
                                  (float*)d_out);
}